// round 13
// baseline (speedup 1.0000x reference)
#include <cuda_runtime.h>
#include <cuda_fp16.h>

#define BATCH   4096
#define FEAT    40960
#define ACCUM   512
#define H1      32
#define MAXIDX  128

// Scratch (device globals — no allocations allowed)
__device__ __half g_ftTh[(size_t)FEAT * ACCUM];   // transposed fp16 weights [FEAT][ACCUM] (42 MB, L2-resident)
__device__ int    g_stm_mode;                     // 0 = byte bool, 1 = int32, 2 = float32

// ---------------------------------------------------------------------------
// K1: transpose + fp32->fp16 convert: ft_w [ACCUM, FEAT] -> g_ftTh [FEAT, ACCUM].
// (Unchanged from R12 winner.)
// ---------------------------------------------------------------------------
__global__ __launch_bounds__(512) void transpose_kernel(
    const float* __restrict__ ftw,
    const unsigned char* __restrict__ stm)
{
    __shared__ float tile[64][33];
    __shared__ int bad_int, bad_f32;

    const int t = threadIdx.x;
    const bool detect = (blockIdx.x == 0 && blockIdx.y == 0);

    if (detect) {
        if (t == 0) { bad_int = 0; bad_f32 = 0; }
        __syncthreads();
        for (int g = t; g < 1024; g += 512) {
            unsigned char b0 = stm[4*g+0], b1 = stm[4*g+1];
            unsigned char b2 = stm[4*g+2], b3 = stm[4*g+3];
            if (!((b1 | b2 | b3) == 0 && b0 <= 1)) atomicOr(&bad_int, 1);
            bool zero = (b0 | b1 | b2 | b3) == 0;
            bool one  = (b0 == 0 && b1 == 0 && b2 == 0x80 && b3 == 0x3F);
            if (!(zero || one)) atomicOr(&bad_f32, 1);
        }
        __syncthreads();
        if (t == 0)
            g_stm_mode = (!bad_int) ? 1 : ((!bad_f32) ? 2 : 0);
        __syncthreads();
    }

    const int fx = blockIdx.x * 64;    // feature tile origin
    const int oy = blockIdx.y * 32;    // accum tile origin

    {
        int a = t >> 4, q = t & 15;
        float4 v = __ldcs((const float4*)&ftw[(size_t)(oy + a) * FEAT + fx + 4*q]);
        tile[4*q + 0][a] = v.x;
        tile[4*q + 1][a] = v.y;
        tile[4*q + 2][a] = v.z;
        tile[4*q + 3][a] = v.w;
    }
    __syncthreads();

    if (t < 256) {
        int f = t >> 2, q = t & 3;
        __half2 h0 = __floats2half2_rn(tile[f][8*q + 0], tile[f][8*q + 1]);
        __half2 h1 = __floats2half2_rn(tile[f][8*q + 2], tile[f][8*q + 3]);
        __half2 h2 = __floats2half2_rn(tile[f][8*q + 4], tile[f][8*q + 5]);
        __half2 h3 = __floats2half2_rn(tile[f][8*q + 6], tile[f][8*q + 7]);
        uint4 o;
        o.x = *reinterpret_cast<unsigned*>(&h0);
        o.y = *reinterpret_cast<unsigned*>(&h1);
        o.z = *reinterpret_cast<unsigned*>(&h2);
        o.w = *reinterpret_cast<unsigned*>(&h3);
        *(uint4*)&g_ftTh[(size_t)(fx + f) * ACCUM + oy + 8*q] = o;
    }
}

// ---------------------------------------------------------------------------
// K2: NNUE forward. One block per batch row, 256 threads, 8 CTAs/SM.
// Same 2048 threads/SM as the 512x4 config, but 8-way phase staggering so
// per-SM DRAM issue duty stays high while individual CTAs gather/MLP.
// ---------------------------------------------------------------------------
__global__ __launch_bounds__(256, 8) void nnue_kernel(
    const float* __restrict__ wf, const float* __restrict__ bf,
    const unsigned char* __restrict__ stm_raw,
    const float* __restrict__ ft_b,
    const float* __restrict__ l1_w, const float* __restrict__ l1_b,
    const float* __restrict__ l2_w, const float* __restrict__ l2_b,
    const float* __restrict__ out_w, const float* __restrict__ out_b,
    float* __restrict__ out)
{
    const int row = blockIdx.x;
    const int t   = threadIdx.x;

    __shared__ float sp[4][ACCUM];     // gather partials (8 KB)
    __shared__ int   idxw[MAXIDX], idxb[MAXIDX];
    __shared__ int   nw, nb;
    __shared__ float x[2 * ACCUM];
    __shared__ float v1s[H1];

    if (t == 0) { nw = 0; nb = 0; }
    __syncthreads();

    // ---- Phase A: scan features — white pass, then black pass ----
    const float4* wrow = (const float4*)(wf + (size_t)row * FEAT);
    const float4* brow = (const float4*)(bf + (size_t)row * FEAT);

    #pragma unroll
    for (int i = 0; i < FEAT / 4 / 256; i++) {   // 40 iterations
        int vi = t + i * 256;
        float4 v = __ldcs(&wrow[vi]);
        if (v.x != 0.f) { int p = atomicAdd(&nw, 1); if (p < MAXIDX) idxw[p] = 4*vi + 0; }
        if (v.y != 0.f) { int p = atomicAdd(&nw, 1); if (p < MAXIDX) idxw[p] = 4*vi + 1; }
        if (v.z != 0.f) { int p = atomicAdd(&nw, 1); if (p < MAXIDX) idxw[p] = 4*vi + 2; }
        if (v.w != 0.f) { int p = atomicAdd(&nw, 1); if (p < MAXIDX) idxw[p] = 4*vi + 3; }
    }
    #pragma unroll
    for (int i = 0; i < FEAT / 4 / 256; i++) {   // 40 iterations
        int vi = t + i * 256;
        float4 u = __ldcs(&brow[vi]);
        if (u.x != 0.f) { int p = atomicAdd(&nb, 1); if (p < MAXIDX) idxb[p] = 4*vi + 0; }
        if (u.y != 0.f) { int p = atomicAdd(&nb, 1); if (p < MAXIDX) idxb[p] = 4*vi + 1; }
        if (u.z != 0.f) { int p = atomicAdd(&nb, 1); if (p < MAXIDX) idxb[p] = 4*vi + 2; }
        if (u.w != 0.f) { int p = atomicAdd(&nb, 1); if (p < MAXIDX) idxb[p] = 4*vi + 3; }
    }
    __syncthreads();

    const int cw = min(nw, MAXIDX), cb = min(nb, MAXIDX);

    const int g = t >> 6;        // gather group 0..3 (feature stride 4)
    const int u = t & 63;        // channel octet: channels 8u..8u+7

    // ---- Phase B1: white gather (fp16 uint4 = 8 channels/thread) ----
    {
        float s0=0.f,s1=0.f,s2=0.f,s3=0.f,s4=0.f,s5=0.f,s6=0.f,s7=0.f;
        #pragma unroll 1
        for (int k = g; k < cw; k += 4) {
            uint4 v = *(const uint4*)&g_ftTh[(size_t)idxw[k] * ACCUM + 8*u];
            float2 f0 = __half22float2(*reinterpret_cast<__half2*>(&v.x));
            float2 f1 = __half22float2(*reinterpret_cast<__half2*>(&v.y));
            float2 f2 = __half22float2(*reinterpret_cast<__half2*>(&v.z));
            float2 f3 = __half22float2(*reinterpret_cast<__half2*>(&v.w));
            s0 += f0.x; s1 += f0.y; s2 += f1.x; s3 += f1.y;
            s4 += f2.x; s5 += f2.y; s6 += f3.x; s7 += f3.y;
        }
        sp[g][8*u + 0] = s0; sp[g][8*u + 1] = s1;
        sp[g][8*u + 2] = s2; sp[g][8*u + 3] = s3;
        sp[g][8*u + 4] = s4; sp[g][8*u + 5] = s5;
        sp[g][8*u + 6] = s6; sp[g][8*u + 7] = s7;
    }
    __syncthreads();
    float accw0 = ft_b[t]       + (sp[0][t]       + sp[1][t])       + (sp[2][t]       + sp[3][t]);
    float accw1 = ft_b[t + 256] + (sp[0][t + 256] + sp[1][t + 256]) + (sp[2][t + 256] + sp[3][t + 256]);
    __syncthreads();

    // ---- Phase B2: black gather ----
    {
        float s0=0.f,s1=0.f,s2=0.f,s3=0.f,s4=0.f,s5=0.f,s6=0.f,s7=0.f;
        #pragma unroll 1
        for (int k = g; k < cb; k += 4) {
            uint4 v = *(const uint4*)&g_ftTh[(size_t)idxb[k] * ACCUM + 8*u];
            float2 f0 = __half22float2(*reinterpret_cast<__half2*>(&v.x));
            float2 f1 = __half22float2(*reinterpret_cast<__half2*>(&v.y));
            float2 f2 = __half22float2(*reinterpret_cast<__half2*>(&v.z));
            float2 f3 = __half22float2(*reinterpret_cast<__half2*>(&v.w));
            s0 += f0.x; s1 += f0.y; s2 += f1.x; s3 += f1.y;
            s4 += f2.x; s5 += f2.y; s6 += f3.x; s7 += f3.y;
        }
        sp[g][8*u + 0] = s0; sp[g][8*u + 1] = s1;
        sp[g][8*u + 2] = s2; sp[g][8*u + 3] = s3;
        sp[g][8*u + 4] = s4; sp[g][8*u + 5] = s5;
        sp[g][8*u + 6] = s6; sp[g][8*u + 7] = s7;
    }
    __syncthreads();
    float accb0 = ft_b[t]       + (sp[0][t]       + sp[1][t])       + (sp[2][t]       + sp[3][t]);
    float accb1 = ft_b[t + 256] + (sp[0][t + 256] + sp[1][t + 256]) + (sp[2][t + 256] + sp[3][t + 256]);

    // screlu (two channels per thread: t and t+256)
    accw0 = fminf(fmaxf(accw0, 0.f), 1.f); accw0 *= accw0;
    accw1 = fminf(fmaxf(accw1, 0.f), 1.f); accw1 *= accw1;
    accb0 = fminf(fmaxf(accb0, 0.f), 1.f); accb0 *= accb0;
    accb1 = fminf(fmaxf(accb1, 0.f), 1.f); accb1 *= accb1;

    // stm select (dtype-mode decoded)
    bool s;
    {
        int mode = g_stm_mode;
        if (mode == 1)      s = ((const int*)stm_raw)[row] != 0;
        else if (mode == 2) s = ((const float*)stm_raw)[row] != 0.f;
        else                s = stm_raw[row] != 0;
    }
    x[t]               = s ? accb0 : accw0;
    x[t + 256]         = s ? accb1 : accw1;
    x[ACCUM + t]       = s ? accw0 : accb0;
    x[ACCUM + t + 256] = s ? accw1 : accb1;
    __syncthreads();

    // ---- Phase C: L1 (32 outputs x 1024 dot), 8 warps x 4 outputs ----
    const int warp = t >> 5, lane = t & 31;
    #pragma unroll
    for (int oo = 0; oo < 4; oo++) {
        int o = warp * 4 + oo;
        const float* w1 = l1_w + (size_t)o * (2 * ACCUM);
        float sum = 0.f;
        #pragma unroll
        for (int j = lane; j < 2 * ACCUM; j += 32)
            sum += x[j] * __ldg(&w1[j]);
        #pragma unroll
        for (int off = 16; off > 0; off >>= 1)
            sum += __shfl_down_sync(0xffffffffu, sum, off);
        if (lane == 0) {
            sum += l1_b[o];
            sum = fminf(fmaxf(sum, 0.f), 1.f);
            v1s[o] = sum * sum;
        }
    }
    __syncthreads();

    // ---- L2 layer + output head (warp 0) ----
    if (warp == 0) {
        float sum = l2_b[lane];
        #pragma unroll
        for (int j = 0; j < H1; j++)
            sum += v1s[j] * __ldg(&l2_w[lane * H1 + j]);
        sum = fminf(fmaxf(sum, 0.f), 1.f);
        float vv = sum * sum * __ldg(&out_w[lane]);
        #pragma unroll
        for (int off = 16; off > 0; off >>= 1)
            vv += __shfl_down_sync(0xffffffffu, vv, off);
        if (lane == 0) out[row] = vv + out_b[0];
    }
}

// ---------------------------------------------------------------------------
extern "C" void kernel_launch(void* const* d_in, const int* in_sizes, int n_in,
                              void* d_out, int out_size) {
    const float*         wf    = (const float*)d_in[0];
    const float*         bf    = (const float*)d_in[1];
    const unsigned char* stm   = (const unsigned char*)d_in[2];
    const float*         ft_w  = (const float*)d_in[3];
    const float*         ft_b  = (const float*)d_in[4];
    const float*         l1_w  = (const float*)d_in[5];
    const float*         l1_b  = (const float*)d_in[6];
    const float*         l2_w  = (const float*)d_in[7];
    const float*         l2_b  = (const float*)d_in[8];
    const float*         out_w = (const float*)d_in[9];
    const float*         out_b = (const float*)d_in[10];
    float*               out   = (float*)d_out;

    dim3 tgrid(FEAT / 64, ACCUM / 32);
    transpose_kernel<<<tgrid, 512>>>(ft_w, stm);

    nnue_kernel<<<BATCH, 256>>>(wf, bf, stm, ft_b, l1_w, l1_b,
                                l2_w, l2_b, out_w, out_b, out);
}

// round 14
// speedup vs baseline: 1.1259x; 1.1259x over previous
#include <cuda_runtime.h>
#include <cuda_fp16.h>

#define BATCH   4096
#define FEAT    40960
#define ACCUM   512
#define H1      32
#define MAXIDX  128

// Scratch (device globals — no allocations allowed)
__device__ __half g_ftTh[(size_t)FEAT * ACCUM];   // transposed fp16 weights [FEAT][ACCUM] (42 MB, L2-resident)
__device__ int    g_stm_mode;                     // 0 = byte bool, 1 = int32, 2 = float32

// ---------------------------------------------------------------------------
// K1: transpose + fp32->fp16 convert: ft_w [ACCUM, FEAT] -> g_ftTh [FEAT, ACCUM].
// (Unchanged from R12 winner.)
// ---------------------------------------------------------------------------
__global__ __launch_bounds__(512) void transpose_kernel(
    const float* __restrict__ ftw,
    const unsigned char* __restrict__ stm)
{
    __shared__ float tile[64][33];
    __shared__ int bad_int, bad_f32;

    const int t = threadIdx.x;
    const bool detect = (blockIdx.x == 0 && blockIdx.y == 0);

    if (detect) {
        if (t == 0) { bad_int = 0; bad_f32 = 0; }
        __syncthreads();
        for (int g = t; g < 1024; g += 512) {
            unsigned char b0 = stm[4*g+0], b1 = stm[4*g+1];
            unsigned char b2 = stm[4*g+2], b3 = stm[4*g+3];
            if (!((b1 | b2 | b3) == 0 && b0 <= 1)) atomicOr(&bad_int, 1);
            bool zero = (b0 | b1 | b2 | b3) == 0;
            bool one  = (b0 == 0 && b1 == 0 && b2 == 0x80 && b3 == 0x3F);
            if (!(zero || one)) atomicOr(&bad_f32, 1);
        }
        __syncthreads();
        if (t == 0)
            g_stm_mode = (!bad_int) ? 1 : ((!bad_f32) ? 2 : 0);
        __syncthreads();
    }

    const int fx = blockIdx.x * 64;    // feature tile origin
    const int oy = blockIdx.y * 32;    // accum tile origin

    {
        int a = t >> 4, q = t & 15;
        float4 v = __ldcs((const float4*)&ftw[(size_t)(oy + a) * FEAT + fx + 4*q]);
        tile[4*q + 0][a] = v.x;
        tile[4*q + 1][a] = v.y;
        tile[4*q + 2][a] = v.z;
        tile[4*q + 3][a] = v.w;
    }
    __syncthreads();

    if (t < 256) {
        int f = t >> 2, q = t & 3;
        __half2 h0 = __floats2half2_rn(tile[f][8*q + 0], tile[f][8*q + 1]);
        __half2 h1 = __floats2half2_rn(tile[f][8*q + 2], tile[f][8*q + 3]);
        __half2 h2 = __floats2half2_rn(tile[f][8*q + 4], tile[f][8*q + 5]);
        __half2 h3 = __floats2half2_rn(tile[f][8*q + 6], tile[f][8*q + 7]);
        uint4 o;
        o.x = *reinterpret_cast<unsigned*>(&h0);
        o.y = *reinterpret_cast<unsigned*>(&h1);
        o.z = *reinterpret_cast<unsigned*>(&h2);
        o.w = *reinterpret_cast<unsigned*>(&h3);
        *(uint4*)&g_ftTh[(size_t)(fx + f) * ACCUM + oy + 8*q] = o;
    }
}

// ---------------------------------------------------------------------------
// K2: NNUE forward. One block per batch row, 512 threads, 4 CTAs/SM.
// (R12 winner structure; gather loads batched; L1 layer float4-vectorized.)
// ---------------------------------------------------------------------------
__global__ __launch_bounds__(512, 4) void nnue_kernel(
    const float* __restrict__ wf, const float* __restrict__ bf,
    const unsigned char* __restrict__ stm_raw,
    const float* __restrict__ ft_b,
    const float* __restrict__ l1_w, const float* __restrict__ l1_b,
    const float* __restrict__ l2_w, const float* __restrict__ l2_b,
    const float* __restrict__ out_w, const float* __restrict__ out_b,
    float* __restrict__ out)
{
    const int row = blockIdx.x;
    const int t   = threadIdx.x;

    __shared__ float  sp[8][ACCUM];        // gather partials (16 KB)
    __shared__ float4 xv[2 * ACCUM / 4];   // L1 input, 16B-aligned (4 KB)
    __shared__ int    idxw[MAXIDX], idxb[MAXIDX];
    __shared__ int    nw, nb;
    __shared__ float  v1s[H1];

    float* x = (float*)xv;

    if (t == 0) { nw = 0; nb = 0; }
    __syncthreads();

    // ---- Phase A: scan features — white pass, then black pass ----
    const float4* wrow = (const float4*)(wf + (size_t)row * FEAT);
    const float4* brow = (const float4*)(bf + (size_t)row * FEAT);

    #pragma unroll
    for (int i = 0; i < FEAT / 4 / 512; i++) {   // 20 iterations
        int vi = t + i * 512;
        float4 v = __ldcs(&wrow[vi]);
        if (v.x != 0.f) { int p = atomicAdd(&nw, 1); if (p < MAXIDX) idxw[p] = 4*vi + 0; }
        if (v.y != 0.f) { int p = atomicAdd(&nw, 1); if (p < MAXIDX) idxw[p] = 4*vi + 1; }
        if (v.z != 0.f) { int p = atomicAdd(&nw, 1); if (p < MAXIDX) idxw[p] = 4*vi + 2; }
        if (v.w != 0.f) { int p = atomicAdd(&nw, 1); if (p < MAXIDX) idxw[p] = 4*vi + 3; }
    }
    #pragma unroll
    for (int i = 0; i < FEAT / 4 / 512; i++) {   // 20 iterations
        int vi = t + i * 512;
        float4 u = __ldcs(&brow[vi]);
        if (u.x != 0.f) { int p = atomicAdd(&nb, 1); if (p < MAXIDX) idxb[p] = 4*vi + 0; }
        if (u.y != 0.f) { int p = atomicAdd(&nb, 1); if (p < MAXIDX) idxb[p] = 4*vi + 1; }
        if (u.z != 0.f) { int p = atomicAdd(&nb, 1); if (p < MAXIDX) idxb[p] = 4*vi + 2; }
        if (u.w != 0.f) { int p = atomicAdd(&nb, 1); if (p < MAXIDX) idxb[p] = 4*vi + 3; }
    }
    __syncthreads();

    const int cw = min(nw, MAXIDX), cb = min(nb, MAXIDX);

    const int g = t >> 6;        // gather group 0..7 (feature stride 8)
    const int u = t & 63;        // channel octet: channels 8u..8u+7

    // ---- Phase B1: white gather (fp16 uint4 = 8 channels/thread) ----
    {
        float s0=0.f,s1=0.f,s2=0.f,s3=0.f,s4=0.f,s5=0.f,s6=0.f,s7=0.f;
        #pragma unroll 2
        for (int k = g; k < cw; k += 8) {
            uint4 v = *(const uint4*)&g_ftTh[(size_t)idxw[k] * ACCUM + 8*u];
            float2 f0 = __half22float2(*reinterpret_cast<__half2*>(&v.x));
            float2 f1 = __half22float2(*reinterpret_cast<__half2*>(&v.y));
            float2 f2 = __half22float2(*reinterpret_cast<__half2*>(&v.z));
            float2 f3 = __half22float2(*reinterpret_cast<__half2*>(&v.w));
            s0 += f0.x; s1 += f0.y; s2 += f1.x; s3 += f1.y;
            s4 += f2.x; s5 += f2.y; s6 += f3.x; s7 += f3.y;
        }
        sp[g][8*u + 0] = s0; sp[g][8*u + 1] = s1;
        sp[g][8*u + 2] = s2; sp[g][8*u + 3] = s3;
        sp[g][8*u + 4] = s4; sp[g][8*u + 5] = s5;
        sp[g][8*u + 6] = s6; sp[g][8*u + 7] = s7;
    }
    __syncthreads();
    float accw = ft_b[t] + ((sp[0][t] + sp[1][t]) + (sp[2][t] + sp[3][t]))
                         + ((sp[4][t] + sp[5][t]) + (sp[6][t] + sp[7][t]));
    __syncthreads();

    // ---- Phase B2: black gather ----
    {
        float s0=0.f,s1=0.f,s2=0.f,s3=0.f,s4=0.f,s5=0.f,s6=0.f,s7=0.f;
        #pragma unroll 2
        for (int k = g; k < cb; k += 8) {
            uint4 v = *(const uint4*)&g_ftTh[(size_t)idxb[k] * ACCUM + 8*u];
            float2 f0 = __half22float2(*reinterpret_cast<__half2*>(&v.x));
            float2 f1 = __half22float2(*reinterpret_cast<__half2*>(&v.y));
            float2 f2 = __half22float2(*reinterpret_cast<__half2*>(&v.z));
            float2 f3 = __half22float2(*reinterpret_cast<__half2*>(&v.w));
            s0 += f0.x; s1 += f0.y; s2 += f1.x; s3 += f1.y;
            s4 += f2.x; s5 += f2.y; s6 += f3.x; s7 += f3.y;
        }
        sp[g][8*u + 0] = s0; sp[g][8*u + 1] = s1;
        sp[g][8*u + 2] = s2; sp[g][8*u + 3] = s3;
        sp[g][8*u + 4] = s4; sp[g][8*u + 5] = s5;
        sp[g][8*u + 6] = s6; sp[g][8*u + 7] = s7;
    }
    __syncthreads();
    float accb = ft_b[t] + ((sp[0][t] + sp[1][t]) + (sp[2][t] + sp[3][t]))
                         + ((sp[4][t] + sp[5][t]) + (sp[6][t] + sp[7][t]));

    // screlu
    accw = fminf(fmaxf(accw, 0.f), 1.f); accw *= accw;
    accb = fminf(fmaxf(accb, 0.f), 1.f); accb *= accb;

    // stm select (dtype-mode decoded)
    bool s;
    {
        int mode = g_stm_mode;
        if (mode == 1)      s = ((const int*)stm_raw)[row] != 0;
        else if (mode == 2) s = ((const float*)stm_raw)[row] != 0.f;
        else                s = stm_raw[row] != 0;
    }
    x[t]         = s ? accb : accw;
    x[ACCUM + t] = s ? accw : accb;
    __syncthreads();

    // ---- Phase C: L1 (32 outputs x 1024 dot), 16 warps x 2 outputs,
    //      float4-vectorized on both x (smem) and l1_w (global) ----
    const int warp = t >> 5, lane = t & 31;
    #pragma unroll
    for (int oo = 0; oo < 2; oo++) {
        int o = warp * 2 + oo;
        const float4* w1v = (const float4*)(l1_w + (size_t)o * (2 * ACCUM));
        float sum = 0.f;
        #pragma unroll
        for (int i = 0; i < (2 * ACCUM) / 4 / 32; i++) {    // 8 iterations
            float4 a = xv[lane + 32 * i];
            float4 b = __ldg(&w1v[lane + 32 * i]);
            sum += a.x * b.x + a.y * b.y + a.z * b.z + a.w * b.w;
        }
        #pragma unroll
        for (int off = 16; off > 0; off >>= 1)
            sum += __shfl_down_sync(0xffffffffu, sum, off);
        if (lane == 0) {
            sum += l1_b[o];
            sum = fminf(fmaxf(sum, 0.f), 1.f);
            v1s[o] = sum * sum;
        }
    }
    __syncthreads();

    // ---- L2 layer + output head (warp 0) ----
    if (warp == 0) {
        float sum = l2_b[lane];
        #pragma unroll
        for (int j = 0; j < H1; j++)
            sum += v1s[j] * __ldg(&l2_w[lane * H1 + j]);
        sum = fminf(fmaxf(sum, 0.f), 1.f);
        float vv = sum * sum * __ldg(&out_w[lane]);
        #pragma unroll
        for (int off = 16; off > 0; off >>= 1)
            vv += __shfl_down_sync(0xffffffffu, vv, off);
        if (lane == 0) out[row] = vv + out_b[0];
    }
}

// ---------------------------------------------------------------------------
extern "C" void kernel_launch(void* const* d_in, const int* in_sizes, int n_in,
                              void* d_out, int out_size) {
    const float*         wf    = (const float*)d_in[0];
    const float*         bf    = (const float*)d_in[1];
    const unsigned char* stm   = (const unsigned char*)d_in[2];
    const float*         ft_w  = (const float*)d_in[3];
    const float*         ft_b  = (const float*)d_in[4];
    const float*         l1_w  = (const float*)d_in[5];
    const float*         l1_b  = (const float*)d_in[6];
    const float*         l2_w  = (const float*)d_in[7];
    const float*         l2_b  = (const float*)d_in[8];
    const float*         out_w = (const float*)d_in[9];
    const float*         out_b = (const float*)d_in[10];
    float*               out   = (float*)d_out;

    dim3 tgrid(FEAT / 64, ACCUM / 32);
    transpose_kernel<<<tgrid, 512>>>(ft_w, stm);

    nnue_kernel<<<BATCH, 512>>>(wf, bf, stm, ft_b, l1_w, l1_b,
                                l2_w, l2_b, out_w, out_b, out);
}

// round 15
// speedup vs baseline: 1.1579x; 1.0284x over previous
#include <cuda_runtime.h>
#include <cuda_fp16.h>

#define BATCH   4096
#define FEAT    40960
#define ACCUM   512
#define H1      32
#define MAXIDX  128

// Scratch (device globals — no allocations allowed)
__device__ __half g_ftTh[(size_t)FEAT * ACCUM];   // transposed fp16 weights [FEAT][ACCUM] (42 MB, L2-resident)
__device__ int    g_stm_mode;                     // 0 = byte bool, 1 = int32, 2 = float32

// ---------------------------------------------------------------------------
// K1: transpose + fp32->fp16 convert: ft_w [ACCUM, FEAT] -> g_ftTh [FEAT, ACCUM].
// (Unchanged from R12 winner.)
// ---------------------------------------------------------------------------
__global__ __launch_bounds__(512) void transpose_kernel(
    const float* __restrict__ ftw,
    const unsigned char* __restrict__ stm)
{
    __shared__ float tile[64][33];
    __shared__ int bad_int, bad_f32;

    const int t = threadIdx.x;
    const bool detect = (blockIdx.x == 0 && blockIdx.y == 0);

    if (detect) {
        if (t == 0) { bad_int = 0; bad_f32 = 0; }
        __syncthreads();
        for (int g = t; g < 1024; g += 512) {
            unsigned char b0 = stm[4*g+0], b1 = stm[4*g+1];
            unsigned char b2 = stm[4*g+2], b3 = stm[4*g+3];
            if (!((b1 | b2 | b3) == 0 && b0 <= 1)) atomicOr(&bad_int, 1);
            bool zero = (b0 | b1 | b2 | b3) == 0;
            bool one  = (b0 == 0 && b1 == 0 && b2 == 0x80 && b3 == 0x3F);
            if (!(zero || one)) atomicOr(&bad_f32, 1);
        }
        __syncthreads();
        if (t == 0)
            g_stm_mode = (!bad_int) ? 1 : ((!bad_f32) ? 2 : 0);
        __syncthreads();
    }

    const int fx = blockIdx.x * 64;    // feature tile origin
    const int oy = blockIdx.y * 32;    // accum tile origin

    {
        int a = t >> 4, q = t & 15;
        float4 v = __ldcs((const float4*)&ftw[(size_t)(oy + a) * FEAT + fx + 4*q]);
        tile[4*q + 0][a] = v.x;
        tile[4*q + 1][a] = v.y;
        tile[4*q + 2][a] = v.z;
        tile[4*q + 3][a] = v.w;
    }
    __syncthreads();

    if (t < 256) {
        int f = t >> 2, q = t & 3;
        __half2 h0 = __floats2half2_rn(tile[f][8*q + 0], tile[f][8*q + 1]);
        __half2 h1 = __floats2half2_rn(tile[f][8*q + 2], tile[f][8*q + 3]);
        __half2 h2 = __floats2half2_rn(tile[f][8*q + 4], tile[f][8*q + 5]);
        __half2 h3 = __floats2half2_rn(tile[f][8*q + 6], tile[f][8*q + 7]);
        uint4 o;
        o.x = *reinterpret_cast<unsigned*>(&h0);
        o.y = *reinterpret_cast<unsigned*>(&h1);
        o.z = *reinterpret_cast<unsigned*>(&h2);
        o.w = *reinterpret_cast<unsigned*>(&h3);
        *(uint4*)&g_ftTh[(size_t)(fx + f) * ACCUM + oy + 8*q] = o;
    }
}

// ---------------------------------------------------------------------------
// K2: NNUE forward. One block per batch row, 512 threads, 4 CTAs/SM.
// R12 winner code with ONE structural change: the white gather is issued in
// the same straight-line region as the black scan (independent loads overlap
// on the scoreboard), and sp is double-buffered (spW/spB) so the black gather
// needs no WAR barrier against the white reduce. Gathers stay unroll 1,
// L1 stays scalar (R14's tweaks regressed and are reverted).
// ---------------------------------------------------------------------------
__global__ __launch_bounds__(512, 4) void nnue_kernel(
    const float* __restrict__ wf, const float* __restrict__ bf,
    const unsigned char* __restrict__ stm_raw,
    const float* __restrict__ ft_b,
    const float* __restrict__ l1_w, const float* __restrict__ l1_b,
    const float* __restrict__ l2_w, const float* __restrict__ l2_b,
    const float* __restrict__ out_w, const float* __restrict__ out_b,
    float* __restrict__ out)
{
    const int row = blockIdx.x;
    const int t   = threadIdx.x;

    __shared__ float spW[8][ACCUM];    // white gather partials (16 KB)
    __shared__ float spB[8][ACCUM];    // black gather partials (16 KB)
    __shared__ int   idxw[MAXIDX], idxb[MAXIDX];
    __shared__ int   nw, nb;
    __shared__ float x[2 * ACCUM];
    __shared__ float v1s[H1];

    if (t == 0) { nw = 0; nb = 0; }
    __syncthreads();

    const float4* wrow = (const float4*)(wf + (size_t)row * FEAT);
    const float4* brow = (const float4*)(bf + (size_t)row * FEAT);

    const int g = t >> 6;        // gather group 0..7 (feature stride 8)
    const int u = t & 63;        // channel octet: channels 8u..8u+7

    // ---- Phase A1: white scan (20 fully-unrolled iterations) ----
    #pragma unroll
    for (int i = 0; i < FEAT / 4 / 512; i++) {
        int vi = t + i * 512;
        float4 v = __ldcs(&wrow[vi]);
        if (v.x != 0.f) { int p = atomicAdd(&nw, 1); if (p < MAXIDX) idxw[p] = 4*vi + 0; }
        if (v.y != 0.f) { int p = atomicAdd(&nw, 1); if (p < MAXIDX) idxw[p] = 4*vi + 1; }
        if (v.z != 0.f) { int p = atomicAdd(&nw, 1); if (p < MAXIDX) idxw[p] = 4*vi + 2; }
        if (v.w != 0.f) { int p = atomicAdd(&nw, 1); if (p < MAXIDX) idxw[p] = 4*vi + 3; }
    }
    __syncthreads();            // idxw / nw final
    const int cw = min(nw, MAXIDX);

    // ---- Phase A2+B1: black scan AND white gather in one region ----
    // (scan-B LDGs front-batch; gather-W L2 loads are independent and
    //  overlap the streaming latency — no barrier in between.)
    #pragma unroll
    for (int i = 0; i < FEAT / 4 / 512; i++) {
        int vi = t + i * 512;
        float4 v = __ldcs(&brow[vi]);
        if (v.x != 0.f) { int p = atomicAdd(&nb, 1); if (p < MAXIDX) idxb[p] = 4*vi + 0; }
        if (v.y != 0.f) { int p = atomicAdd(&nb, 1); if (p < MAXIDX) idxb[p] = 4*vi + 1; }
        if (v.z != 0.f) { int p = atomicAdd(&nb, 1); if (p < MAXIDX) idxb[p] = 4*vi + 2; }
        if (v.w != 0.f) { int p = atomicAdd(&nb, 1); if (p < MAXIDX) idxb[p] = 4*vi + 3; }
    }
    {
        float s0=0.f,s1=0.f,s2=0.f,s3=0.f,s4=0.f,s5=0.f,s6=0.f,s7=0.f;
        #pragma unroll 1
        for (int k = g; k < cw; k += 8) {
            uint4 v = *(const uint4*)&g_ftTh[(size_t)idxw[k] * ACCUM + 8*u];
            float2 f0 = __half22float2(*reinterpret_cast<__half2*>(&v.x));
            float2 f1 = __half22float2(*reinterpret_cast<__half2*>(&v.y));
            float2 f2 = __half22float2(*reinterpret_cast<__half2*>(&v.z));
            float2 f3 = __half22float2(*reinterpret_cast<__half2*>(&v.w));
            s0 += f0.x; s1 += f0.y; s2 += f1.x; s3 += f1.y;
            s4 += f2.x; s5 += f2.y; s6 += f3.x; s7 += f3.y;
        }
        spW[g][8*u + 0] = s0; spW[g][8*u + 1] = s1;
        spW[g][8*u + 2] = s2; spW[g][8*u + 3] = s3;
        spW[g][8*u + 4] = s4; spW[g][8*u + 5] = s5;
        spW[g][8*u + 6] = s6; spW[g][8*u + 7] = s7;
    }
    __syncthreads();            // spW complete + idxb / nb final
    const int cb = min(nb, MAXIDX);

    // ---- white reduce (reads spW) ----
    float accw = ft_b[t] + ((spW[0][t] + spW[1][t]) + (spW[2][t] + spW[3][t]))
                         + ((spW[4][t] + spW[5][t]) + (spW[6][t] + spW[7][t]));

    // ---- black gather into spB (no WAR hazard vs spW reads) ----
    {
        float s0=0.f,s1=0.f,s2=0.f,s3=0.f,s4=0.f,s5=0.f,s6=0.f,s7=0.f;
        #pragma unroll 1
        for (int k = g; k < cb; k += 8) {
            uint4 v = *(const uint4*)&g_ftTh[(size_t)idxb[k] * ACCUM + 8*u];
            float2 f0 = __half22float2(*reinterpret_cast<__half2*>(&v.x));
            float2 f1 = __half22float2(*reinterpret_cast<__half2*>(&v.y));
            float2 f2 = __half22float2(*reinterpret_cast<__half2*>(&v.z));
            float2 f3 = __half22float2(*reinterpret_cast<__half2*>(&v.w));
            s0 += f0.x; s1 += f0.y; s2 += f1.x; s3 += f1.y;
            s4 += f2.x; s5 += f2.y; s6 += f3.x; s7 += f3.y;
        }
        spB[g][8*u + 0] = s0; spB[g][8*u + 1] = s1;
        spB[g][8*u + 2] = s2; spB[g][8*u + 3] = s3;
        spB[g][8*u + 4] = s4; spB[g][8*u + 5] = s5;
        spB[g][8*u + 6] = s6; spB[g][8*u + 7] = s7;
    }
    __syncthreads();            // spB complete
    float accb = ft_b[t] + ((spB[0][t] + spB[1][t]) + (spB[2][t] + spB[3][t]))
                         + ((spB[4][t] + spB[5][t]) + (spB[6][t] + spB[7][t]));

    // screlu
    accw = fminf(fmaxf(accw, 0.f), 1.f); accw *= accw;
    accb = fminf(fmaxf(accb, 0.f), 1.f); accb *= accb;

    // stm select (dtype-mode decoded)
    bool s;
    {
        int mode = g_stm_mode;
        if (mode == 1)      s = ((const int*)stm_raw)[row] != 0;
        else if (mode == 2) s = ((const float*)stm_raw)[row] != 0.f;
        else                s = stm_raw[row] != 0;
    }
    x[t]         = s ? accb : accw;
    x[ACCUM + t] = s ? accw : accb;
    __syncthreads();

    // ---- Phase C: L1 (32 outputs x 1024 dot), 16 warps x 2 outputs ----
    const int warp = t >> 5, lane = t & 31;
    #pragma unroll
    for (int oo = 0; oo < 2; oo++) {
        int o = warp * 2 + oo;
        const float* w1 = l1_w + (size_t)o * (2 * ACCUM);
        float sum = 0.f;
        #pragma unroll
        for (int j = lane; j < 2 * ACCUM; j += 32)
            sum += x[j] * __ldg(&w1[j]);
        #pragma unroll
        for (int off = 16; off > 0; off >>= 1)
            sum += __shfl_down_sync(0xffffffffu, sum, off);
        if (lane == 0) {
            sum += l1_b[o];
            sum = fminf(fmaxf(sum, 0.f), 1.f);
            v1s[o] = sum * sum;
        }
    }
    __syncthreads();

    // ---- L2 layer + output head (warp 0) ----
    if (warp == 0) {
        float sum = l2_b[lane];
        #pragma unroll
        for (int j = 0; j < H1; j++)
            sum += v1s[j] * __ldg(&l2_w[lane * H1 + j]);
        sum = fminf(fmaxf(sum, 0.f), 1.f);
        float vv = sum * sum * __ldg(&out_w[lane]);
        #pragma unroll
        for (int off = 16; off > 0; off >>= 1)
            vv += __shfl_down_sync(0xffffffffu, vv, off);
        if (lane == 0) out[row] = vv + out_b[0];
    }
}

// ---------------------------------------------------------------------------
extern "C" void kernel_launch(void* const* d_in, const int* in_sizes, int n_in,
                              void* d_out, int out_size) {
    const float*         wf    = (const float*)d_in[0];
    const float*         bf    = (const float*)d_in[1];
    const unsigned char* stm   = (const unsigned char*)d_in[2];
    const float*         ft_w  = (const float*)d_in[3];
    const float*         ft_b  = (const float*)d_in[4];
    const float*         l1_w  = (const float*)d_in[5];
    const float*         l1_b  = (const float*)d_in[6];
    const float*         l2_w  = (const float*)d_in[7];
    const float*         l2_b  = (const float*)d_in[8];
    const float*         out_w = (const float*)d_in[9];
    const float*         out_b = (const float*)d_in[10];
    float*               out   = (float*)d_out;

    dim3 tgrid(FEAT / 64, ACCUM / 32);
    transpose_kernel<<<tgrid, 512>>>(ft_w, stm);

    nnue_kernel<<<BATCH, 512>>>(wf, bf, stm, ft_b, l1_w, l1_b,
                                l2_w, l2_b, out_w, out_b, out);
}

// round 16
// speedup vs baseline: 1.1788x; 1.0180x over previous
#include <cuda_runtime.h>
#include <cuda_fp16.h>

#define BATCH   4096
#define FEAT    40960
#define ACCUM   512
#define H1      32
#define MAXIDX  128

// Scratch (device globals — no allocations allowed)
__device__ __half g_ftTh[(size_t)FEAT * ACCUM];   // transposed fp16 weights [FEAT][ACCUM] (42 MB, L2-resident)
__device__ int    g_stm_mode;                     // 0 = byte bool, 1 = int32, 2 = float32

// ---------------------------------------------------------------------------
// K1: transpose + fp32->fp16 convert, CHUNKED: grid (640, 2), each block
// handles a 64-feat stripe x 8 accum-subtiles (32 each), with the next
// chunk's LDG.128 prefetched into registers before the store phase so DRAM
// latency overlaps the smem write-out. 8x fewer blocks than R12's version.
// Block (0,0) additionally detects the stm dtype (first 4096 bytes only).
// ---------------------------------------------------------------------------
__global__ __launch_bounds__(512) void transpose_kernel(
    const float* __restrict__ ftw,
    const unsigned char* __restrict__ stm)
{
    __shared__ float tile[64][33];
    __shared__ int bad_int, bad_f32;

    const int t = threadIdx.x;
    const bool detect = (blockIdx.x == 0 && blockIdx.y == 0);

    if (detect) {
        if (t == 0) { bad_int = 0; bad_f32 = 0; }
        __syncthreads();
        for (int g = t; g < 1024; g += 512) {
            unsigned char b0 = stm[4*g+0], b1 = stm[4*g+1];
            unsigned char b2 = stm[4*g+2], b3 = stm[4*g+3];
            if (!((b1 | b2 | b3) == 0 && b0 <= 1)) atomicOr(&bad_int, 1);
            bool zero = (b0 | b1 | b2 | b3) == 0;
            bool one  = (b0 == 0 && b1 == 0 && b2 == 0x80 && b3 == 0x3F);
            if (!(zero || one)) atomicOr(&bad_f32, 1);
        }
        __syncthreads();
        if (t == 0)
            g_stm_mode = (!bad_int) ? 1 : ((!bad_f32) ? 2 : 0);
        __syncthreads();
    }

    const int fx  = blockIdx.x * 64;          // feature stripe origin
    const int oy0 = blockIdx.y * 256;         // accum range origin (8 x 32)

    const int a = t >> 4, q = t & 15;         // load indexing
    const int f = t >> 2, qq = t & 3;         // store indexing (t < 256)

    float4 v = __ldcs((const float4*)&ftw[(size_t)(oy0 + a) * FEAT + fx + 4*q]);

    #pragma unroll
    for (int i = 0; i < 8; i++) {
        const int oy = oy0 + i * 32;

        tile[4*q + 0][a] = v.x;
        tile[4*q + 1][a] = v.y;
        tile[4*q + 2][a] = v.z;
        tile[4*q + 3][a] = v.w;
        __syncthreads();

        // prefetch next chunk while the store phase runs
        if (i < 7)
            v = __ldcs((const float4*)&ftw[(size_t)(oy + 32 + a) * FEAT + fx + 4*q]);

        if (t < 256) {
            __half2 h0 = __floats2half2_rn(tile[f][8*qq + 0], tile[f][8*qq + 1]);
            __half2 h1 = __floats2half2_rn(tile[f][8*qq + 2], tile[f][8*qq + 3]);
            __half2 h2 = __floats2half2_rn(tile[f][8*qq + 4], tile[f][8*qq + 5]);
            __half2 h3 = __floats2half2_rn(tile[f][8*qq + 6], tile[f][8*qq + 7]);
            uint4 o;
            o.x = *reinterpret_cast<unsigned*>(&h0);
            o.y = *reinterpret_cast<unsigned*>(&h1);
            o.z = *reinterpret_cast<unsigned*>(&h2);
            o.w = *reinterpret_cast<unsigned*>(&h3);
            *(uint4*)&g_ftTh[(size_t)(fx + f) * ACCUM + oy + 8*qq] = o;
        }
        __syncthreads();
    }
}

// ---------------------------------------------------------------------------
// K2: NNUE forward. One block per batch row, 512 threads, 4 CTAs/SM.
// (Byte-identical to the R15 kernel — best measured nnue at 234.6 us.)
// ---------------------------------------------------------------------------
__global__ __launch_bounds__(512, 4) void nnue_kernel(
    const float* __restrict__ wf, const float* __restrict__ bf,
    const unsigned char* __restrict__ stm_raw,
    const float* __restrict__ ft_b,
    const float* __restrict__ l1_w, const float* __restrict__ l1_b,
    const float* __restrict__ l2_w, const float* __restrict__ l2_b,
    const float* __restrict__ out_w, const float* __restrict__ out_b,
    float* __restrict__ out)
{
    const int row = blockIdx.x;
    const int t   = threadIdx.x;

    __shared__ float spW[8][ACCUM];    // white gather partials (16 KB)
    __shared__ float spB[8][ACCUM];    // black gather partials (16 KB)
    __shared__ int   idxw[MAXIDX], idxb[MAXIDX];
    __shared__ int   nw, nb;
    __shared__ float x[2 * ACCUM];
    __shared__ float v1s[H1];

    if (t == 0) { nw = 0; nb = 0; }
    __syncthreads();

    const float4* wrow = (const float4*)(wf + (size_t)row * FEAT);
    const float4* brow = (const float4*)(bf + (size_t)row * FEAT);

    const int g = t >> 6;        // gather group 0..7 (feature stride 8)
    const int u = t & 63;        // channel octet: channels 8u..8u+7

    // ---- Phase A1: white scan (20 fully-unrolled iterations) ----
    #pragma unroll
    for (int i = 0; i < FEAT / 4 / 512; i++) {
        int vi = t + i * 512;
        float4 v = __ldcs(&wrow[vi]);
        if (v.x != 0.f) { int p = atomicAdd(&nw, 1); if (p < MAXIDX) idxw[p] = 4*vi + 0; }
        if (v.y != 0.f) { int p = atomicAdd(&nw, 1); if (p < MAXIDX) idxw[p] = 4*vi + 1; }
        if (v.z != 0.f) { int p = atomicAdd(&nw, 1); if (p < MAXIDX) idxw[p] = 4*vi + 2; }
        if (v.w != 0.f) { int p = atomicAdd(&nw, 1); if (p < MAXIDX) idxw[p] = 4*vi + 3; }
    }
    __syncthreads();            // idxw / nw final
    const int cw = min(nw, MAXIDX);

    // ---- Phase A2+B1: black scan AND white gather in one region ----
    #pragma unroll
    for (int i = 0; i < FEAT / 4 / 512; i++) {
        int vi = t + i * 512;
        float4 v = __ldcs(&brow[vi]);
        if (v.x != 0.f) { int p = atomicAdd(&nb, 1); if (p < MAXIDX) idxb[p] = 4*vi + 0; }
        if (v.y != 0.f) { int p = atomicAdd(&nb, 1); if (p < MAXIDX) idxb[p] = 4*vi + 1; }
        if (v.z != 0.f) { int p = atomicAdd(&nb, 1); if (p < MAXIDX) idxb[p] = 4*vi + 2; }
        if (v.w != 0.f) { int p = atomicAdd(&nb, 1); if (p < MAXIDX) idxb[p] = 4*vi + 3; }
    }
    {
        float s0=0.f,s1=0.f,s2=0.f,s3=0.f,s4=0.f,s5=0.f,s6=0.f,s7=0.f;
        #pragma unroll 1
        for (int k = g; k < cw; k += 8) {
            uint4 v = *(const uint4*)&g_ftTh[(size_t)idxw[k] * ACCUM + 8*u];
            float2 f0 = __half22float2(*reinterpret_cast<__half2*>(&v.x));
            float2 f1 = __half22float2(*reinterpret_cast<__half2*>(&v.y));
            float2 f2 = __half22float2(*reinterpret_cast<__half2*>(&v.z));
            float2 f3 = __half22float2(*reinterpret_cast<__half2*>(&v.w));
            s0 += f0.x; s1 += f0.y; s2 += f1.x; s3 += f1.y;
            s4 += f2.x; s5 += f2.y; s6 += f3.x; s7 += f3.y;
        }
        spW[g][8*u + 0] = s0; spW[g][8*u + 1] = s1;
        spW[g][8*u + 2] = s2; spW[g][8*u + 3] = s3;
        spW[g][8*u + 4] = s4; spW[g][8*u + 5] = s5;
        spW[g][8*u + 6] = s6; spW[g][8*u + 7] = s7;
    }
    __syncthreads();            // spW complete + idxb / nb final
    const int cb = min(nb, MAXIDX);

    // ---- white reduce (reads spW) ----
    float accw = ft_b[t] + ((spW[0][t] + spW[1][t]) + (spW[2][t] + spW[3][t]))
                         + ((spW[4][t] + spW[5][t]) + (spW[6][t] + spW[7][t]));

    // ---- black gather into spB (no WAR hazard vs spW reads) ----
    {
        float s0=0.f,s1=0.f,s2=0.f,s3=0.f,s4=0.f,s5=0.f,s6=0.f,s7=0.f;
        #pragma unroll 1
        for (int k = g; k < cb; k += 8) {
            uint4 v = *(const uint4*)&g_ftTh[(size_t)idxb[k] * ACCUM + 8*u];
            float2 f0 = __half22float2(*reinterpret_cast<__half2*>(&v.x));
            float2 f1 = __half22float2(*reinterpret_cast<__half2*>(&v.y));
            float2 f2 = __half22float2(*reinterpret_cast<__half2*>(&v.z));
            float2 f3 = __half22float2(*reinterpret_cast<__half2*>(&v.w));
            s0 += f0.x; s1 += f0.y; s2 += f1.x; s3 += f1.y;
            s4 += f2.x; s5 += f2.y; s6 += f3.x; s7 += f3.y;
        }
        spB[g][8*u + 0] = s0; spB[g][8*u + 1] = s1;
        spB[g][8*u + 2] = s2; spB[g][8*u + 3] = s3;
        spB[g][8*u + 4] = s4; spB[g][8*u + 5] = s5;
        spB[g][8*u + 6] = s6; spB[g][8*u + 7] = s7;
    }
    __syncthreads();            // spB complete
    float accb = ft_b[t] + ((spB[0][t] + spB[1][t]) + (spB[2][t] + spB[3][t]))
                         + ((spB[4][t] + spB[5][t]) + (spB[6][t] + spB[7][t]));

    // screlu
    accw = fminf(fmaxf(accw, 0.f), 1.f); accw *= accw;
    accb = fminf(fmaxf(accb, 0.f), 1.f); accb *= accb;

    // stm select (dtype-mode decoded)
    bool s;
    {
        int mode = g_stm_mode;
        if (mode == 1)      s = ((const int*)stm_raw)[row] != 0;
        else if (mode == 2) s = ((const float*)stm_raw)[row] != 0.f;
        else                s = stm_raw[row] != 0;
    }
    x[t]         = s ? accb : accw;
    x[ACCUM + t] = s ? accw : accb;
    __syncthreads();

    // ---- Phase C: L1 (32 outputs x 1024 dot), 16 warps x 2 outputs ----
    const int warp = t >> 5, lane = t & 31;
    #pragma unroll
    for (int oo = 0; oo < 2; oo++) {
        int o = warp * 2 + oo;
        const float* w1 = l1_w + (size_t)o * (2 * ACCUM);
        float sum = 0.f;
        #pragma unroll
        for (int j = lane; j < 2 * ACCUM; j += 32)
            sum += x[j] * __ldg(&w1[j]);
        #pragma unroll
        for (int off = 16; off > 0; off >>= 1)
            sum += __shfl_down_sync(0xffffffffu, sum, off);
        if (lane == 0) {
            sum += l1_b[o];
            sum = fminf(fmaxf(sum, 0.f), 1.f);
            v1s[o] = sum * sum;
        }
    }
    __syncthreads();

    // ---- L2 layer + output head (warp 0) ----
    if (warp == 0) {
        float sum = l2_b[lane];
        #pragma unroll
        for (int j = 0; j < H1; j++)
            sum += v1s[j] * __ldg(&l2_w[lane * H1 + j]);
        sum = fminf(fmaxf(sum, 0.f), 1.f);
        float vv = sum * sum * __ldg(&out_w[lane]);
        #pragma unroll
        for (int off = 16; off > 0; off >>= 1)
            vv += __shfl_down_sync(0xffffffffu, vv, off);
        if (lane == 0) out[row] = vv + out_b[0];
    }
}

// ---------------------------------------------------------------------------
extern "C" void kernel_launch(void* const* d_in, const int* in_sizes, int n_in,
                              void* d_out, int out_size) {
    const float*         wf    = (const float*)d_in[0];
    const float*         bf    = (const float*)d_in[1];
    const unsigned char* stm   = (const unsigned char*)d_in[2];
    const float*         ft_w  = (const float*)d_in[3];
    const float*         ft_b  = (const float*)d_in[4];
    const float*         l1_w  = (const float*)d_in[5];
    const float*         l1_b  = (const float*)d_in[6];
    const float*         l2_w  = (const float*)d_in[7];
    const float*         l2_b  = (const float*)d_in[8];
    const float*         out_w = (const float*)d_in[9];
    const float*         out_b = (const float*)d_in[10];
    float*               out   = (float*)d_out;

    dim3 tgrid(FEAT / 64, ACCUM / 256);   // (640, 2)
    transpose_kernel<<<tgrid, 512>>>(ft_w, stm);

    nnue_kernel<<<BATCH, 512>>>(wf, bf, stm, ft_b, l1_w, l1_b,
                                l2_w, l2_b, out_w, out_b, out);
}